// round 2
// baseline (speedup 1.0000x reference)
#include <cuda_runtime.h>
#include <math.h>

// Problem shape (fixed by the dataset)
constexpr int B  = 2;
constexpr int C  = 64;
constexpr int H  = 180;
constexpr int W  = 360;
constexpr int HW = H * W;
constexpr int Hp = H + 2;
constexpr int Wp = W + 2;
constexpr int TP = 32;          // pixels per block
constexpr float TWO_PI = 6.28318530717958647692f;

__device__ float g_stats[4];    // min_lat, max_lat, min_lon, max_lon

// ---------------------------------------------------------------------------
// Kernel 1: min/max of lat_grid / lon_grid (single block)
// ---------------------------------------------------------------------------
__global__ void stats_kernel(const float* __restrict__ lat,
                             const float* __restrict__ lon, int n)
{
    float mnla = 1e30f, mxla = -1e30f, mnlo = 1e30f, mxlo = -1e30f;
    for (int i = threadIdx.x; i < n; i += blockDim.x) {
        float a = lat[i];
        mnla = fminf(mnla, a); mxla = fmaxf(mxla, a);
        float o = lon[i];
        mnlo = fminf(mnlo, o); mxlo = fmaxf(mxlo, o);
    }
#pragma unroll
    for (int off = 16; off > 0; off >>= 1) {
        mnla = fminf(mnla, __shfl_xor_sync(0xffffffffu, mnla, off));
        mxla = fmaxf(mxla, __shfl_xor_sync(0xffffffffu, mxla, off));
        mnlo = fminf(mnlo, __shfl_xor_sync(0xffffffffu, mnlo, off));
        mxlo = fmaxf(mxlo, __shfl_xor_sync(0xffffffffu, mxlo, off));
    }
    __shared__ float s[4][32];
    int lane = threadIdx.x & 31, wid = threadIdx.x >> 5;
    if (lane == 0) { s[0][wid] = mnla; s[1][wid] = mxla; s[2][wid] = mnlo; s[3][wid] = mxlo; }
    __syncthreads();
    if (wid == 0) {
        int nw = blockDim.x >> 5;
        mnla = (lane < nw) ? s[0][lane] :  1e30f;
        mxla = (lane < nw) ? s[1][lane] : -1e30f;
        mnlo = (lane < nw) ? s[2][lane] :  1e30f;
        mxlo = (lane < nw) ? s[3][lane] : -1e30f;
#pragma unroll
        for (int off = 16; off > 0; off >>= 1) {
            mnla = fminf(mnla, __shfl_xor_sync(0xffffffffu, mnla, off));
            mxla = fmaxf(mxla, __shfl_xor_sync(0xffffffffu, mxla, off));
            mnlo = fminf(mnlo, __shfl_xor_sync(0xffffffffu, mnlo, off));
            mxlo = fmaxf(mxlo, __shfl_xor_sync(0xffffffffu, mxlo, off));
        }
        if (lane == 0) {
            g_stats[0] = mnla; g_stats[1] = mxla;
            g_stats[2] = mnlo; g_stats[3] = mxlo;
        }
    }
}

// ---------------------------------------------------------------------------
// Bicubic weights (A = -0.75), matching reference _cubic_weights exactly
// ---------------------------------------------------------------------------
__device__ __forceinline__ void cubic_w(float t, float w[4])
{
    const float A = -0.75f;
    float x;
    x = t + 1.0f;  w[0] = ((A * x - 5.0f * A) * x + 8.0f * A) * x - 4.0f * A;
    x = t;         w[1] = ((A + 2.0f) * x - (A + 3.0f)) * x * x + 1.0f;
    x = 1.0f - t;  w[2] = ((A + 2.0f) * x - (A + 3.0f)) * x * x + 1.0f;
    x = 2.0f - t;  w[3] = ((A * x - 5.0f * A) * x + 8.0f * A) * x - 4.0f * A;
}

// ---------------------------------------------------------------------------
// Fused main kernel: projection + departure point + bicubic sample
// Block: 256 threads, covers 32 pixels x 64 channels of one batch.
// ---------------------------------------------------------------------------
__global__ __launch_bounds__(256)
void nsl_kernel(const float* __restrict__ hidden,
                const float* __restrict__ latg,
                const float* __restrict__ long_,
                const float* __restrict__ Wv,
                const float* __restrict__ bv,
                const float* __restrict__ dtp,
                float* __restrict__ out)
{
    __shared__ float sW[128][64];       // 32 KB  (later overlaid by u/v)
    __shared__ float sX[64][TP];        // 8 KB
    __shared__ float s_sp[TP], s_cp[TP], s_lonp[TP];

    const int blk  = blockIdx.x;
    const int b    = blk / (HW / TP);
    const int tile = blk % (HW / TP);
    const int pix0 = tile * TP;
    const int tid  = threadIdx.x;
    const float dt = dtp[0];

    // --- stage W_vel (128x64) into shared via float4 ---
    {
        const float4* Wv4 = (const float4*)Wv;
        float4* sW4 = (float4*)&sW[0][0];
        for (int i = tid; i < (128 * 64) / 4; i += 256) sW4[i] = Wv4[i];
    }
    // --- stage hidden tile: sX[k][p] = hidden[b,k,pix0+p] ---
    for (int i = tid; i < 64 * TP; i += 256) {
        int k = i / TP, p = i % TP;
        sX[k][p] = hidden[((size_t)b * C + k) * HW + pix0 + p];
    }
    // --- per-pixel trig of the arrival grid ---
    if (tid < TP) {
        float la = latg[b * HW + pix0 + tid];
        float lo = long_[b * HW + pix0 + tid];
        float sp, cp;
        sincosf(la, &sp, &cp);
        s_sp[tid] = sp; s_cp[tid] = cp; s_lonp[tid] = lo;
    }
    __syncthreads();

    const int p  = tid & (TP - 1);
    const int cg = tid >> 5;            // 0..7 -> channel group of 8

    // --- projection: u_c, v_c for 8 channels of this thread ---
    float u[8], v[8];
#pragma unroll
    for (int j = 0; j < 8; j++) {
        int c = cg * 8 + j;
        u[j] = bv[c];
        v[j] = bv[C + c];
    }
    for (int k = 0; k < 64; k += 4) {
        float x0 = sX[k][p], x1 = sX[k + 1][p], x2 = sX[k + 2][p], x3 = sX[k + 3][p];
#pragma unroll
        for (int j = 0; j < 8; j++) {
            int c = cg * 8 + j;
            float4 wu = *(const float4*)&sW[c][k];
            float4 wv = *(const float4*)&sW[64 + c][k];
            u[j] = fmaf(x0, wu.x, fmaf(x1, wu.y, fmaf(x2, wu.z, fmaf(x3, wu.w, u[j]))));
            v[j] = fmaf(x0, wv.x, fmaf(x1, wv.y, fmaf(x2, wv.z, fmaf(x3, wv.w, v[j]))));
        }
    }
    __syncthreads();   // everyone done reading sW -> safe to overlay

    // stage u,v into shared (overlay sW region) so the element loop stays
    // rolled without local-memory spills
    float* sU = &sW[0][0];              // [64][TP]
    float* sV = sU + 64 * TP;           // [64][TP]
#pragma unroll
    for (int j = 0; j < 8; j++) {
        int c = cg * 8 + j;
        sU[c * TP + p] = u[j];
        sV[c * TP + p] = v[j];
    }
    __syncthreads();

    // per-pixel constants
    const float sp   = s_sp[p];
    const float cp   = s_cp[p];
    const float lonp = s_lonp[p];
    const int   pix  = pix0 + p;

    const float minla = g_stats[0], maxla = g_stats[1];
    const float minlo = g_stats[2], maxlo = g_stats[3];
    const float gxs = 2.0f / (maxlo - minlo);
    const float gys = 2.0f / (maxla - minla);

#pragma unroll 1
    for (int j = 0; j < 8; j++) {
        const int c = cg * 8 + j;
        const float uu = sU[c * TP + p];
        const float vv = sV[c * TP + p];

        // departure point on the sphere
        float lon_pr = -uu * dt;
        float lat_pr = -vv * dt;
        float slp, clp, slo, clo;
        sincosf(lat_pr, &slp, &clp);
        sincosf(lon_pr, &slo, &clo);

        float sin_lat = slp * cp + clp * clo * sp;
        sin_lat = fminf(fmaxf(sin_lat, -1.0f + 1e-7f), 1.0f - 1e-7f);
        float lat = asinf(sin_lat);

        float num = clp * slo;
        float den = clp * clo * cp - slp * sp;
        float lx  = lonp + atan2f(num, den) + TWO_PI;
        float lon = lx - floorf(lx * (1.0f / TWO_PI)) * TWO_PI;   // remainder(., 2pi)

        // normalized grid coords
        float gx = (lon - minlo) * gxs - 1.0f;
        float gy = (lat - minla) * gys - 1.0f;

        // wrap gx to [-1, 1)
        float t = gx + 1.0f;
        t = t - floorf(t * 0.5f) * 2.0f;
        gx = t - 1.0f;

        bool left  = gx <= 0.0f;
        bool outer = fabsf(gy) > 1.0f;
        if (outer) gx += left ? 1.0f : -1.0f;
        if (gy < -1.0f)      gy = -(2.0f + gy);
        else if (gy > 1.0f)  gy = 2.0f - gy;

        gx *= (float)W / (float)Wp;
        gy *= (float)H / (float)Hp;

        // bicubic sample of the (virtually) padded field
        float ix = (gx + 1.0f) * 0.5f * (float)(Wp - 1);
        float iy = (gy + 1.0f) * 0.5f * (float)(Hp - 1);
        float fx0 = floorf(ix), fy0 = floorf(iy);
        float tx = ix - fx0,  ty = iy - fy0;
        int ix0 = (int)fx0,   iy0 = (int)fy0;

        float wx[4], wy[4];
        cubic_w(tx, wx);
        cubic_w(ty, wy);

        const float* base = hidden + ((size_t)b * C + c) * HW;
        float acc = 0.0f;
#pragma unroll
        for (int jj = 0; jj < 4; jj++) {
            int yy = iy0 + jj - 1;
            yy = min(max(yy, 0), Hp - 1);
            int  row;
            bool wrapped;
            if (yy == 0)            { row = 0;      wrapped = true;  }
            else if (yy == Hp - 1)  { row = H - 1;  wrapped = true;  }
            else                    { row = yy - 1; wrapped = false; }
            float rowacc = 0.0f;
#pragma unroll
            for (int ii = 0; ii < 4; ii++) {
                int xx = ix0 + ii - 1;
                xx = min(max(xx, 0), Wp - 1);
                int col = (xx == 0) ? (W - 1) : ((xx == Wp - 1) ? 0 : (xx - 1));
                if (wrapped) col = (col + W / 2) % W;   // roll by W/2 in padded rows
                rowacc = fmaf(wx[ii], base[row * W + col], rowacc);
            }
            acc = fmaf(wy[jj], rowacc, acc);
        }
        out[((size_t)b * C + c) * HW + pix] = acc;
    }
}

// ---------------------------------------------------------------------------
extern "C" void kernel_launch(void* const* d_in, const int* in_sizes, int n_in,
                              void* d_out, int out_size)
{
    const float* hidden = (const float*)d_in[0];
    const float* latg   = (const float*)d_in[1];
    const float* long_  = (const float*)d_in[2];
    const float* Wv     = (const float*)d_in[3];
    const float* bv     = (const float*)d_in[4];
    const float* dtp    = (const float*)d_in[5];
    float* out          = (float*)d_out;

    stats_kernel<<<1, 1024>>>(latg, long_, in_sizes[1]);
    nsl_kernel<<<B * (HW / TP), 256>>>(hidden, latg, long_, Wv, bv, dtp, out);
}

// round 3
// speedup vs baseline: 1.3103x; 1.3103x over previous
#include <cuda_runtime.h>
#include <math.h>

constexpr int B  = 2;
constexpr int C  = 64;
constexpr int H  = 180;
constexpr int W  = 360;
constexpr int HW = H * W;              // 64800
constexpr int Hp = H + 2;              // 182
constexpr int Wp = W + 2;              // 362
constexpr int NTILES = (B * HW) / 32;  // 4050 32-pixel tiles
constexpr int TILES_PER_BLK = 4;       // 128 pixels / block
constexpr int PBLK = 128;
constexpr int NPT = (NTILES + TILES_PER_BLK - 1) / TILES_PER_BLK;  // 1013
constexpr float TWO_PI = 6.283185307179586f;

__device__ unsigned g_keys[4];  // enc(min_lat), enc(max_lat), enc(min_lon), enc(max_lon)

__device__ __forceinline__ unsigned fenc(float f) {
    unsigned u = __float_as_uint(f);
    return (u & 0x80000000u) ? ~u : (u | 0x80000000u);
}
__device__ __forceinline__ float fdec(unsigned e) {
    return __uint_as_float((e & 0x80000000u) ? (e ^ 0x80000000u) : ~e);
}

__global__ void reset_kernel() {
    if (threadIdx.x == 0) {
        g_keys[0] = 0xFFFFFFFFu; g_keys[1] = 0u;
        g_keys[2] = 0xFFFFFFFFu; g_keys[3] = 0u;
    }
}

__global__ void stats_kernel(const float* __restrict__ lat,
                             const float* __restrict__ lon, int n)
{
    unsigned mnla = 0xFFFFFFFFu, mxla = 0u, mnlo = 0xFFFFFFFFu, mxlo = 0u;
    for (int i = blockIdx.x * blockDim.x + threadIdx.x; i < n; i += gridDim.x * blockDim.x) {
        unsigned a = fenc(lat[i]); mnla = min(mnla, a); mxla = max(mxla, a);
        unsigned o = fenc(lon[i]); mnlo = min(mnlo, o); mxlo = max(mxlo, o);
    }
#pragma unroll
    for (int off = 16; off; off >>= 1) {
        mnla = min(mnla, __shfl_xor_sync(0xffffffffu, mnla, off));
        mxla = max(mxla, __shfl_xor_sync(0xffffffffu, mxla, off));
        mnlo = min(mnlo, __shfl_xor_sync(0xffffffffu, mnlo, off));
        mxlo = max(mxlo, __shfl_xor_sync(0xffffffffu, mxlo, off));
    }
    if ((threadIdx.x & 31) == 0) {
        atomicMin(&g_keys[0], mnla); atomicMax(&g_keys[1], mxla);
        atomicMin(&g_keys[2], mnlo); atomicMax(&g_keys[3], mxlo);
    }
}

// Bicubic weights (A = -0.75), matching reference exactly
__device__ __forceinline__ void cubic_w(float t, float w[4])
{
    const float A = -0.75f;
    float x;
    x = t + 1.0f;  w[0] = ((A * x - 5.0f * A) * x + 8.0f * A) * x - 4.0f * A;
    x = t;         w[1] = ((A + 2.0f) * x - (A + 3.0f)) * x * x + 1.0f;
    x = 1.0f - t;  w[2] = ((A + 2.0f) * x - (A + 3.0f)) * x * x + 1.0f;
    x = 2.0f - t;  w[3] = ((A * x - 5.0f * A) * x + 8.0f * A) * x - 4.0f * A;
}

// fast atan2, poly max err ~1e-6 rad
__device__ __forceinline__ float fast_atan2f(float y, float x)
{
    float ax = fabsf(x), ay = fabsf(y);
    float mx = fmaxf(ax, ay), mn = fminf(ax, ay);
    float a = (mx == 0.0f) ? 0.0f : __fdividef(mn, mx);
    float s = a * a;
    float r = fmaf(s, fmaf(s, fmaf(s, fmaf(s, fmaf(s, -0.0117212f, 0.05265332f),
                  -0.11643287f), 0.19354346f), -0.33262347f), 0.99997726f) * a;
    if (ay > ax)   r = 1.57079637f - r;
    if (x < 0.0f)  r = 3.14159274f - r;
    return (y < 0.0f) ? -r : r;
}

// ---------------------------------------------------------------------------
// Fused kernel. Block = 256 threads, covers 128 pixels x 32 output channels.
// blockIdx: bit0 = channel half, rest = pixel tile group (4 x 32-pixel tiles).
// ---------------------------------------------------------------------------
__global__ __launch_bounds__(256, 4)
void nsl_kernel(const float* __restrict__ hidden,
                const float* __restrict__ latg,
                const float* __restrict__ long_,
                const float* __restrict__ Wv,
                const float* __restrict__ bv,
                const float* __restrict__ dtp,
                float* __restrict__ out)
{
    __shared__ float pool[8192];                 // 32KB: sX[64][128] -> sU[32][128]+sV[32][128]
    __shared__ float s_sp[PBLK], s_cp[PBLK], s_lonp[PBLK];

    const int tid   = threadIdx.x;
    const int chalf = blockIdx.x & 1;
    const int ptile = blockIdx.x >> 1;
    const int t0    = ptile * TILES_PER_BLK;
    const int co0   = chalf * 32;                // first output channel of this block
    const float dt  = dtp[0];

    // ---- phase 0: stage hidden tile sX[k][p] (p = s*32 + j), zero-fill invalid tiles
    for (int i = tid; i < 2048; i += 256) {
        int k = i >> 5;
        int s = (i >> 3) & 3;
        int f = i & 7;
        int t = t0 + s;
        float4 val = make_float4(0.f, 0.f, 0.f, 0.f);
        if (t < NTILES) {
            int b    = (t >= 2025) ? 1 : 0;
            int pixb = (t - b * 2025) * 32;
            val = *(const float4*)&hidden[((size_t)(b * C + k)) * HW + pixb + f * 4];
        }
        *(float4*)&pool[k * 128 + s * 32 + f * 4] = val;
    }
    __syncthreads();

    // ---- per-pixel trig of the arrival grid (128 threads)
    if (tid < PBLK) {
        int t = t0 + (tid >> 5);
        if (t < NTILES) {
            int b   = (t >= 2025) ? 1 : 0;
            int pix = (t - b * 2025) * 32 + (tid & 31);
            float la = latg[b * HW + pix];
            float lo = long_[b * HW + pix];
            float sp, cp;
            __sincosf(la, &sp, &cp);
            s_sp[tid] = sp; s_cp[tid] = cp; s_lonp[tid] = lo;
        }
    }

    // ---- phase 1: projection. warp w: channels co0+w*4..+3; lane: 4 pixels
    const int w  = tid >> 5;
    const int l  = tid & 31;
    const int c0 = co0 + w * 4;
    const int p0 = l * 4;

    float au[4][4], av[4][4];
#pragma unroll
    for (int cc = 0; cc < 4; cc++) {
        float bu = __ldg(&bv[c0 + cc]);
        float bw = __ldg(&bv[C + c0 + cc]);
#pragma unroll
        for (int px = 0; px < 4; px++) { au[cc][px] = bu; av[cc][px] = bw; }
    }

    for (int kk = 0; kk < 64; kk += 4) {
        float x[4][4];
#pragma unroll
        for (int dk = 0; dk < 4; dk++) {
            float4 v = *(const float4*)&pool[(kk + dk) * 128 + p0];
            x[dk][0] = v.x; x[dk][1] = v.y; x[dk][2] = v.z; x[dk][3] = v.w;
        }
#pragma unroll
        for (int cc = 0; cc < 4; cc++) {
            int c = c0 + cc;
            float4 wu = __ldg((const float4*)&Wv[c * 64 + kk]);
            float4 wv = __ldg((const float4*)&Wv[(C + c) * 64 + kk]);
#pragma unroll
            for (int px = 0; px < 4; px++) {
                au[cc][px] = fmaf(wu.x, x[0][px], fmaf(wu.y, x[1][px],
                             fmaf(wu.z, x[2][px], fmaf(wu.w, x[3][px], au[cc][px]))));
                av[cc][px] = fmaf(wv.x, x[0][px], fmaf(wv.y, x[1][px],
                             fmaf(wv.z, x[2][px], fmaf(wv.w, x[3][px], av[cc][px]))));
            }
        }
    }
    __syncthreads();   // all sX reads done -> overlay u/v

    float* sU = pool;              // [32][128]
    float* sV = pool + 32 * 128;   // [32][128]
#pragma unroll
    for (int cc = 0; cc < 4; cc++) {
        *(float4*)&sU[(w * 4 + cc) * 128 + p0] = make_float4(au[cc][0], au[cc][1], au[cc][2], au[cc][3]);
        *(float4*)&sV[(w * 4 + cc) * 128 + p0] = make_float4(av[cc][0], av[cc][1], av[cc][2], av[cc][3]);
    }
    __syncthreads();

    // ---- phase 2: departure point + bicubic gather. thread: 1 pixel x 16 channels
    const int p    = tid & 127;
    const int half = tid >> 7;
    const int t    = t0 + (p >> 5);
    if (t >= NTILES) return;
    const int b   = (t >= 2025) ? 1 : 0;
    const int pix = (t - b * 2025) * 32 + (p & 31);

    const float sp = s_sp[p], cp = s_cp[p], lonp = s_lonp[p];

    const float minla = fdec(g_keys[0]), maxla = fdec(g_keys[1]);
    const float minlo = fdec(g_keys[2]), maxlo = fdec(g_keys[3]);
    const float gxsc = 2.0f / (maxlo - minlo);
    const float gysc = 2.0f / (maxla - minla);

    const float* basep = hidden + (size_t)b * C * HW;
    float* outp = out + ((size_t)b * C + co0) * HW + pix;

#pragma unroll 1
    for (int j = 0; j < 16; j++) {
        const int cl = half * 16 + j;                // local channel 0..31
        const float uu = sU[cl * 128 + p];
        const float vv = sV[cl * 128 + p];

        float lon_pr = -uu * dt;
        float lat_pr = -vv * dt;
        float slp, clp, slo, clo;
        __sincosf(lat_pr, &slp, &clp);
        __sincosf(lon_pr, &slo, &clo);

        float sin_lat = fmaf(slp, cp, clp * clo * sp);
        sin_lat = fminf(fmaxf(sin_lat, -1.0f + 1e-7f), 1.0f - 1e-7f);
        float lat = asinf(sin_lat);

        float num = clp * slo;
        float den = clp * clo * cp - slp * sp;
        float lx  = lonp + fast_atan2f(num, den) + TWO_PI;
        float lon = lx - floorf(lx * (1.0f / TWO_PI)) * TWO_PI;

        float gx = fmaf(lon - minlo, gxsc, -1.0f);
        float gy = fmaf(lat - minla, gysc, -1.0f);

        float tw = gx + 1.0f;
        tw -= floorf(tw * 0.5f) * 2.0f;
        gx = tw - 1.0f;

        bool left  = gx <= 0.0f;
        bool outer = fabsf(gy) > 1.0f;
        if (outer)           gx += left ? 1.0f : -1.0f;
        if (gy < -1.0f)      gy = -(2.0f + gy);
        else if (gy > 1.0f)  gy = 2.0f - gy;

        gx *= (float)W / (float)Wp;
        gy *= (float)H / (float)Hp;

        float ix = (gx + 1.0f) * (0.5f * (float)(Wp - 1));
        float iy = (gy + 1.0f) * (0.5f * (float)(Hp - 1));
        float fx0 = floorf(ix), fy0 = floorf(iy);
        float tx = ix - fx0, ty = iy - fy0;
        int ix0 = (int)fx0, iy0 = (int)fy0;

        float wx[4], wy[4];
        cubic_w(tx, wx);
        cubic_w(ty, wy);

        // hoisted column indices: plain + pole-rolled variants
        int colp[4], colw[4];
#pragma unroll
        for (int ii = 0; ii < 4; ii++) {
            int xx  = min(max(ix0 + ii - 1, 0), Wp - 1);
            int col = (xx == 0) ? (W - 1) : ((xx == Wp - 1) ? 0 : (xx - 1));
            colp[ii] = col;
            int cw = col + W / 2; if (cw >= W) cw -= W;
            colw[ii] = cw;
        }

        const float* base = basep + (size_t)(co0 + cl) * HW;
        float acc = 0.0f;
#pragma unroll
        for (int jj = 0; jj < 4; jj++) {
            int  yy      = min(max(iy0 + jj - 1, 0), Hp - 1);
            bool wrapped = (yy == 0) || (yy == Hp - 1);
            int  row     = (yy == 0) ? 0 : ((yy == Hp - 1) ? (H - 1) : (yy - 1));
            const float* rp = base + row * W;
            int c0i = wrapped ? colw[0] : colp[0];
            int c1i = wrapped ? colw[1] : colp[1];
            int c2i = wrapped ? colw[2] : colp[2];
            int c3i = wrapped ? colw[3] : colp[3];
            float ra =          wx[0] * __ldg(&rp[c0i]);
            ra = fmaf(wx[1], __ldg(&rp[c1i]), ra);
            ra = fmaf(wx[2], __ldg(&rp[c2i]), ra);
            ra = fmaf(wx[3], __ldg(&rp[c3i]), ra);
            acc = fmaf(wy[jj], ra, acc);
        }
        outp[cl * HW] = acc;
    }
}

// ---------------------------------------------------------------------------
extern "C" void kernel_launch(void* const* d_in, const int* in_sizes, int n_in,
                              void* d_out, int out_size)
{
    const float* hidden = (const float*)d_in[0];
    const float* latg   = (const float*)d_in[1];
    const float* long_  = (const float*)d_in[2];
    const float* Wv     = (const float*)d_in[3];
    const float* bv     = (const float*)d_in[4];
    const float* dtp    = (const float*)d_in[5];
    float* out          = (float*)d_out;

    reset_kernel<<<1, 32>>>();
    stats_kernel<<<96, 256>>>(latg, long_, in_sizes[1]);
    nsl_kernel<<<2 * NPT, 256>>>(hidden, latg, long_, Wv, bv, dtp, out);
}

// round 5
// speedup vs baseline: 1.5387x; 1.1743x over previous
#include <cuda_runtime.h>
#include <math.h>

constexpr int B  = 2;
constexpr int C  = 64;
constexpr int H  = 180;
constexpr int W  = 360;
constexpr int HW = H * W;              // 64800
constexpr int Hp = H + 2;              // 182
constexpr int Wp = W + 2;              // 362
constexpr int NTILES = (B * HW) / 32;  // 4050 32-pixel tiles
constexpr int TILES_PER_BLK = 4;       // 128 pixels / block
constexpr int PBLK = 128;
constexpr int NPT = (NTILES + TILES_PER_BLK - 1) / TILES_PER_BLK;  // 1013
constexpr int STATS_BLOCKS = 32;
constexpr float TWO_PI = 6.283185307179586f;

__device__ uint4 g_part[STATS_BLOCKS];  // per-block {enc_min_lat, enc_max_lat, enc_min_lon, enc_max_lon}

__device__ __forceinline__ unsigned fenc(float f) {
    unsigned u = __float_as_uint(f);
    return (u & 0x80000000u) ? ~u : (u | 0x80000000u);
}
__device__ __forceinline__ float fdec(unsigned e) {
    return __uint_as_float((e & 0x80000000u) ? (e ^ 0x80000000u) : ~e);
}

__global__ void stats_kernel(const float* __restrict__ lat,
                             const float* __restrict__ lon, int n)
{
    unsigned mnla = 0xFFFFFFFFu, mxla = 0u, mnlo = 0xFFFFFFFFu, mxlo = 0u;
    for (int i = blockIdx.x * blockDim.x + threadIdx.x; i < n; i += gridDim.x * blockDim.x) {
        unsigned a = fenc(lat[i]); mnla = min(mnla, a); mxla = max(mxla, a);
        unsigned o = fenc(lon[i]); mnlo = min(mnlo, o); mxlo = max(mxlo, o);
    }
#pragma unroll
    for (int off = 16; off; off >>= 1) {
        mnla = min(mnla, __shfl_xor_sync(0xffffffffu, mnla, off));
        mxla = max(mxla, __shfl_xor_sync(0xffffffffu, mxla, off));
        mnlo = min(mnlo, __shfl_xor_sync(0xffffffffu, mnlo, off));
        mxlo = max(mxlo, __shfl_xor_sync(0xffffffffu, mxlo, off));
    }
    __shared__ unsigned s[4][8];
    int lane = threadIdx.x & 31, wid = threadIdx.x >> 5;
    if (lane == 0) { s[0][wid] = mnla; s[1][wid] = mxla; s[2][wid] = mnlo; s[3][wid] = mxlo; }
    __syncthreads();
    if (wid == 0) {
        mnla = (lane < 8) ? s[0][lane] : 0xFFFFFFFFu;
        mxla = (lane < 8) ? s[1][lane] : 0u;
        mnlo = (lane < 8) ? s[2][lane] : 0xFFFFFFFFu;
        mxlo = (lane < 8) ? s[3][lane] : 0u;
#pragma unroll
        for (int off = 4; off; off >>= 1) {
            mnla = min(mnla, __shfl_xor_sync(0xffffffffu, mnla, off));
            mxla = max(mxla, __shfl_xor_sync(0xffffffffu, mxla, off));
            mnlo = min(mnlo, __shfl_xor_sync(0xffffffffu, mnlo, off));
            mxlo = max(mxlo, __shfl_xor_sync(0xffffffffu, mxlo, off));
        }
        if (lane == 0) g_part[blockIdx.x] = make_uint4(mnla, mxla, mnlo, mxlo);
    }
}

// Bicubic weights (A = -0.75), matching reference exactly
__device__ __forceinline__ void cubic_w(float t, float w[4])
{
    const float A = -0.75f;
    float x;
    x = t + 1.0f;  w[0] = ((A * x - 5.0f * A) * x + 8.0f * A) * x - 4.0f * A;
    x = t;         w[1] = ((A + 2.0f) * x - (A + 3.0f)) * x * x + 1.0f;
    x = 1.0f - t;  w[2] = ((A + 2.0f) * x - (A + 3.0f)) * x * x + 1.0f;
    x = 2.0f - t;  w[3] = ((A * x - 5.0f * A) * x + 8.0f * A) * x - 4.0f * A;
}

// fast atan2, poly max err ~1e-6 rad
__device__ __forceinline__ float fast_atan2f(float y, float x)
{
    float ax = fabsf(x), ay = fabsf(y);
    float mx = fmaxf(ax, ay), mn = fminf(ax, ay);
    float a = (mx == 0.0f) ? 0.0f : __fdividef(mn, mx);
    float s = a * a;
    float r = fmaf(s, fmaf(s, fmaf(s, fmaf(s, fmaf(s, -0.0117212f, 0.05265332f),
                  -0.11643287f), 0.19354346f), -0.33262347f), 0.99997726f) * a;
    if (ay > ax)   r = 1.57079637f - r;
    if (x < 0.0f)  r = 3.14159274f - r;
    return (y < 0.0f) ? -r : r;
}

// ---------------------------------------------------------------------------
// Fused kernel. Block = 256 threads, covers 128 pixels x 32 output channels.
// ---------------------------------------------------------------------------
__global__ __launch_bounds__(256, 3)
void nsl_kernel(const float* __restrict__ hidden,
                const float* __restrict__ latg,
                const float* __restrict__ long_,
                const float* __restrict__ Wv,
                const float* __restrict__ bv,
                const float* __restrict__ dtp,
                float* __restrict__ out)
{
    __shared__ float pool[8192];                 // 32KB: sX[64][128] -> sU[32][128]+sV[32][128]
    __shared__ float s_sp[PBLK], s_cp[PBLK], s_lonp[PBLK];
    __shared__ float s_stats[4];

    const int tid   = threadIdx.x;
    const int chalf = blockIdx.x & 1;
    const int ptile = blockIdx.x >> 1;
    const int t0    = ptile * TILES_PER_BLK;
    const int co0   = chalf * 32;                // first output channel of this block
    const float dt  = dtp[0];

    // ---- phase 0: stage hidden tile sX[k][p] (p = s*32 + j), zero-fill invalid tiles
    for (int i = tid; i < 2048; i += 256) {
        int k = i >> 5;
        int s = (i >> 3) & 3;
        int f = i & 7;
        int t = t0 + s;
        float4 val = make_float4(0.f, 0.f, 0.f, 0.f);
        if (t < NTILES) {
            int b    = (t >= 2025) ? 1 : 0;
            int pixb = (t - b * 2025) * 32;
            val = *(const float4*)&hidden[((size_t)(b * C + k)) * HW + pixb + f * 4];
        }
        *(float4*)&pool[k * 128 + s * 32 + f * 4] = val;
    }

    // ---- per-pixel trig of the arrival grid (warps 0-3) + stats reduce (warp 4)
    if (tid < PBLK) {
        int t = t0 + (tid >> 5);
        if (t < NTILES) {
            int b   = (t >= 2025) ? 1 : 0;
            int pix = (t - b * 2025) * 32 + (tid & 31);
            float la = latg[b * HW + pix];
            float lo = long_[b * HW + pix];
            float sp, cp;
            __sincosf(la, &sp, &cp);
            s_sp[tid] = sp; s_cp[tid] = cp; s_lonp[tid] = lo;
        }
    } else if (tid < PBLK + 32) {
        int l = tid - PBLK;
        uint4 v = g_part[l];
        unsigned mnla = v.x, mxla = v.y, mnlo = v.z, mxlo = v.w;
#pragma unroll
        for (int off = 16; off; off >>= 1) {
            mnla = min(mnla, __shfl_xor_sync(0xffffffffu, mnla, off));
            mxla = max(mxla, __shfl_xor_sync(0xffffffffu, mxla, off));
            mnlo = min(mnlo, __shfl_xor_sync(0xffffffffu, mnlo, off));
            mxlo = max(mxlo, __shfl_xor_sync(0xffffffffu, mxlo, off));
        }
        if (l == 0) {
            s_stats[0] = fdec(mnla); s_stats[1] = fdec(mxla);
            s_stats[2] = fdec(mnlo); s_stats[3] = fdec(mxlo);
        }
    }
    __syncthreads();

    // ---- phase 1: projection. warp w: channels co0+w*4..+3; lane: 4 pixels
    const int w  = tid >> 5;
    const int l  = tid & 31;
    const int c0 = co0 + w * 4;
    const int p0 = l * 4;

    float au[4][4], av[4][4];
#pragma unroll
    for (int cc = 0; cc < 4; cc++) {
        float bu = __ldg(&bv[c0 + cc]);
        float bw = __ldg(&bv[C + c0 + cc]);
#pragma unroll
        for (int px = 0; px < 4; px++) { au[cc][px] = bu; av[cc][px] = bw; }
    }

    for (int kk = 0; kk < 64; kk += 4) {
        float x[4][4];
#pragma unroll
        for (int dk = 0; dk < 4; dk++) {
            float4 v = *(const float4*)&pool[(kk + dk) * 128 + p0];
            x[dk][0] = v.x; x[dk][1] = v.y; x[dk][2] = v.z; x[dk][3] = v.w;
        }
#pragma unroll
        for (int cc = 0; cc < 4; cc++) {
            int c = c0 + cc;
            float4 wu = __ldg((const float4*)&Wv[c * 64 + kk]);
            float4 wv = __ldg((const float4*)&Wv[(C + c) * 64 + kk]);
#pragma unroll
            for (int px = 0; px < 4; px++) {
                au[cc][px] = fmaf(wu.x, x[0][px], fmaf(wu.y, x[1][px],
                             fmaf(wu.z, x[2][px], fmaf(wu.w, x[3][px], au[cc][px]))));
                av[cc][px] = fmaf(wv.x, x[0][px], fmaf(wv.y, x[1][px],
                             fmaf(wv.z, x[2][px], fmaf(wv.w, x[3][px], av[cc][px]))));
            }
        }
    }
    __syncthreads();   // all sX reads done -> overlay u/v

    float* sU = pool;              // [32][128]
    float* sV = pool + 32 * 128;   // [32][128]
#pragma unroll
    for (int cc = 0; cc < 4; cc++) {
        *(float4*)&sU[(w * 4 + cc) * 128 + p0] = make_float4(au[cc][0], au[cc][1], au[cc][2], au[cc][3]);
        *(float4*)&sV[(w * 4 + cc) * 128 + p0] = make_float4(av[cc][0], av[cc][1], av[cc][2], av[cc][3]);
    }
    __syncthreads();

    // ---- phase 2: departure point + bicubic gather. thread: 1 pixel x 16 channels
    const int p    = tid & 127;
    const int half = tid >> 7;
    const int t    = t0 + (p >> 5);
    if (t >= NTILES) return;
    const int b   = (t >= 2025) ? 1 : 0;
    const int pix = (t - b * 2025) * 32 + (p & 31);

    const float sp = s_sp[p], cp = s_cp[p], lonp = s_lonp[p];

    const float minla = s_stats[0], maxla = s_stats[1];
    const float minlo = s_stats[2], maxlo = s_stats[3];
    const float gxsc = 2.0f / (maxlo - minlo);
    const float gysc = 2.0f / (maxla - minla);

    const float* basep = hidden + (size_t)b * C * HW;
    float* outp = out + ((size_t)b * C + co0) * HW + pix;

#pragma unroll 2
    for (int j = 0; j < 16; j++) {
        const int cl = half * 16 + j;                // local channel 0..31
        const float uu = sU[cl * 128 + p];
        const float vv = sV[cl * 128 + p];

        float lon_pr = -uu * dt;
        float lat_pr = -vv * dt;
        float slp, clp, slo, clo;
        __sincosf(lat_pr, &slp, &clp);
        __sincosf(lon_pr, &slo, &clo);

        float sin_lat = fmaf(slp, cp, clp * clo * sp);
        sin_lat = fminf(fmaxf(sin_lat, -1.0f + 1e-7f), 1.0f - 1e-7f);
        float lat = asinf(sin_lat);

        float num = clp * slo;
        float den = clp * clo * cp - slp * sp;
        float lx  = lonp + fast_atan2f(num, den) + TWO_PI;
        float lon = lx - floorf(lx * (1.0f / TWO_PI)) * TWO_PI;

        float gx = fmaf(lon - minlo, gxsc, -1.0f);
        float gy = fmaf(lat - minla, gysc, -1.0f);

        float tw = gx + 1.0f;
        tw -= floorf(tw * 0.5f) * 2.0f;
        gx = tw - 1.0f;

        bool left  = gx <= 0.0f;
        bool outer = fabsf(gy) > 1.0f;
        if (outer)           gx += left ? 1.0f : -1.0f;
        if (gy < -1.0f)      gy = -(2.0f + gy);
        else if (gy > 1.0f)  gy = 2.0f - gy;

        gx *= (float)W / (float)Wp;
        gy *= (float)H / (float)Hp;

        float ix = (gx + 1.0f) * (0.5f * (float)(Wp - 1));
        float iy = (gy + 1.0f) * (0.5f * (float)(Hp - 1));
        int ix0 = __float2int_rd(ix);
        int iy0 = __float2int_rd(iy);
        float tx = ix - (float)ix0;
        float ty = iy - (float)iy0;

        float wx[4], wy[4];
        cubic_w(tx, wx);
        cubic_w(ty, wy);

        // hoisted column indices: plain + pole-rolled variants
        int colp[4], colw[4];
#pragma unroll
        for (int ii = 0; ii < 4; ii++) {
            int xx  = min(max(ix0 + ii - 1, 0), Wp - 1);
            int col = (xx == 0) ? (W - 1) : ((xx == Wp - 1) ? 0 : (xx - 1));
            colp[ii] = col;
            int cw = col + W / 2; if (cw >= W) cw -= W;
            colw[ii] = cw;
        }

        const float* base = basep + (size_t)(co0 + cl) * HW;
        float acc = 0.0f;
#pragma unroll
        for (int jj = 0; jj < 4; jj++) {
            int  yy      = min(max(iy0 + jj - 1, 0), Hp - 1);
            bool wrapped = (yy == 0) || (yy == Hp - 1);
            int  row     = (yy == 0) ? 0 : ((yy == Hp - 1) ? (H - 1) : (yy - 1));
            const float* rp = base + row * W;
            int c0i = wrapped ? colw[0] : colp[0];
            int c1i = wrapped ? colw[1] : colp[1];
            int c2i = wrapped ? colw[2] : colp[2];
            int c3i = wrapped ? colw[3] : colp[3];
            float ra =          wx[0] * __ldg(&rp[c0i]);
            ra = fmaf(wx[1], __ldg(&rp[c1i]), ra);
            ra = fmaf(wx[2], __ldg(&rp[c2i]), ra);
            ra = fmaf(wx[3], __ldg(&rp[c3i]), ra);
            acc = fmaf(wy[jj], ra, acc);
        }
        outp[cl * HW] = acc;
    }
}

// ---------------------------------------------------------------------------
extern "C" void kernel_launch(void* const* d_in, const int* in_sizes, int n_in,
                              void* d_out, int out_size)
{
    const float* hidden = (const float*)d_in[0];
    const float* latg   = (const float*)d_in[1];
    const float* long_  = (const float*)d_in[2];
    const float* Wv     = (const float*)d_in[3];
    const float* bv     = (const float*)d_in[4];
    const float* dtp    = (const float*)d_in[5];
    float* out          = (float*)d_out;

    stats_kernel<<<STATS_BLOCKS, 256>>>(latg, long_, in_sizes[1]);
    nsl_kernel<<<2 * NPT, 256>>>(hidden, latg, long_, Wv, bv, dtp, out);
}